// round 7
// baseline (speedup 1.0000x reference)
#include <cuda_runtime.h>
#include <math_constants.h>

#define BATCH    8192
#define OBSD     32
#define HDIM     256
#define CDIM     16
#define NCODE    512
#define ROWS     (BATCH * OBSD)     // 262144

#define ETR      128                // rows per encoder block
#define ETHREADS 512

#define DTR      32
#define DTHREADS 256
#define KC       32

// ---------------- device scratch ----------------
__device__ float g_q[(size_t)ROWS * CDIM];          // quantized decoder input
__device__ float g_t[OBSD * HDIM];                  // sorted breakpoints [d][rank]
// PWL tables: [d][s][0..255]=A (slope), [256..511]=B (intercept incl. b1)
__device__ float g_tab[(size_t)OBSD * (HDIM + 1) * (2 * HDIM)];   // 32*257*512

// ---------------- packed f32x2 helpers ----------------
typedef unsigned long long u64;
__device__ __forceinline__ u64 f2pack(float lo, float hi) {
    u64 r; asm("mov.b64 %0, {%1, %2};" : "=l"(r) : "f"(lo), "f"(hi)); return r;
}
__device__ __forceinline__ u64 ffma2(u64 a, u64 b, u64 c) {
    u64 d; asm("fma.rn.f32x2 %0, %1, %2, %3;" : "=l"(d) : "l"(a), "l"(b), "l"(c)); return d;
}
__device__ __forceinline__ u64 fmul2(u64 a, u64 b) {
    u64 d; asm("mul.rn.f32x2 %0, %1, %2;" : "=l"(d) : "l"(a), "l"(b)); return d;
}
__device__ __forceinline__ u64 fadd2(u64 a, u64 b) {
    u64 d; asm("add.rn.f32x2 %0, %1, %2;" : "=l"(d) : "l"(a), "l"(b)); return d;
}
__device__ __forceinline__ float f2lo(u64 v) { return __uint_as_float((unsigned)v); }
__device__ __forceinline__ float f2hi(u64 v) { return __uint_as_float((unsigned)(v >> 32)); }

// Neumaier compensated add
__device__ __forceinline__ void kadd(float& s, float& c, float y) {
    float t = s + y;
    c += (fabsf(s) >= fabsf(y)) ? ((s - t) + y) : ((y - t) + s);
    s = t;
}

// ======================= PWL table builder =======================
// grid 32 (one block per factor d), 256 threads.
__global__ void pwl_build_kernel(const float* __restrict__ W0,
                                 const float* __restrict__ b0,
                                 const float* __restrict__ W1,
                                 const float* __restrict__ b1)
{
    __shared__ float st[HDIM], swv[HDIM], scv[HDIM];
    __shared__ int   sord[HDIM], sact[HDIM];

    const int d = blockIdx.x;
    const int k = threadIdx.x;

    // h0[b,d,k] = relu(w_k * x + c_k),  w_k = W0[0,k],  c_k = W0[1+d,k] + b0[k]
    float w = W0[k];
    float c = W0[(1 + d) * HDIM + k] + b0[k];
    int act; float t;   // act=1: term activates when x crosses t upward
    if (w > 0.f)      { act = 1; t = -c / w; }
    else if (w < 0.f) { act = 0; t = -c / w; }
    else              { act = (c <= 0.f) ? 1 : 0; t = CUDART_INF_F; }
    st[k] = t; swv[k] = w; scv[k] = c; sact[k] = act;
    __syncthreads();

    // rank by breakpoint (ties broken by index) -> sorted order
    int rank = 0;
    for (int k2 = 0; k2 < HDIM; k2++) {
        float t2 = st[k2];
        rank += (t2 < t || (t2 == t && k2 < k)) ? 1 : 0;
    }
    sord[rank] = k;
    g_t[d * HDIM + rank] = t;
    __syncthreads();

    // prefix sums over segments; thread j owns output column j
    const int j = k;
    float As = 0.f, Ac = 0.f, Bs = 0.f, Bc = 0.f;

    // segment 0 (x = -inf): active set = all !act terms
    for (int kk0 = 0; kk0 < HDIM; kk0 += 8) {
        float w1v[8];
        #pragma unroll
        for (int u = 0; u < 8; u++) w1v[u] = W1[(kk0 + u) * HDIM + j];
        #pragma unroll
        for (int u = 0; u < 8; u++) {
            int kk = kk0 + u;
            if (!sact[kk]) {
                kadd(As, Ac, swv[kk] * w1v[u]);
                kadd(Bs, Bc, scv[kk] * w1v[u]);
            }
        }
    }
    const float bj = b1[j];
    float* tab = g_tab + (size_t)d * (HDIM + 1) * (2 * HDIM);
    tab[j] = As + Ac;
    tab[HDIM + j] = Bs + Bc + bj;

    // walk segments 1..256
    for (int s0 = 1; s0 <= HDIM; s0 += 8) {
        int   kks[8];
        float w1v[8];
        #pragma unroll
        for (int u = 0; u < 8; u++) {
            kks[u] = sord[s0 - 1 + u];
            w1v[u] = W1[kks[u] * HDIM + j];
        }
        #pragma unroll
        for (int u = 0; u < 8; u++) {
            int kk = kks[u];
            float sgn = sact[kk] ? 1.f : -1.f;
            kadd(As, Ac, sgn * swv[kk] * w1v[u]);
            kadd(Bs, Bc, sgn * scv[kk] * w1v[u]);
            int s = s0 + u;
            tab[(size_t)s * (2 * HDIM) + j] = As + Ac;
            tab[(size_t)s * (2 * HDIM) + HDIM + j] = Bs + Bc + bj;
        }
    }
}

// ---------------- encoder shared-memory layout (floats) ----------------
#define E_SH    0                  // h1 [128][260]           = 33280
#define E_W2    33280              // 256*16                  =  4096
#define E_CB    37376              // 512*16                  =  8192
#define E_CN    45568              // 512
#define E_SE    46080              // 128*16                  =  2048
#define E_OB    48128              // 128
#define E_T     48256              // 32*256 sorted breakpts  =  8192
#define E_SMEM_FLOATS 56448
#define E_SMEM_BYTES  (E_SMEM_FLOATS * 4)   // 225792

// ======================= encoder (PWL) + quantize =======================
__global__ __launch_bounds__(ETHREADS, 1)
void enc_pwl_kernel(const float* __restrict__ obs,
                    const float* __restrict__ W2,
                    const float* __restrict__ b2,
                    const float* __restrict__ cb)
{
    extern __shared__ float sm[];
    const int tid  = threadIdx.x;
    const int base = blockIdx.x * ETR;

    // ---- stage obs, W2, codebook, breakpoints ----
    if (tid < ETR) sm[E_OB + tid] = obs[base + tid];
    {
        const float4* s = (const float4*)W2;
        float4* dst = (float4*)(sm + E_W2);
        for (int i = tid; i < (HDIM * CDIM) / 4; i += ETHREADS) dst[i] = s[i];
    }
    {
        const float4* s = (const float4*)cb;
        float4* dst = (float4*)(sm + E_CB);
        for (int i = tid; i < (NCODE * CDIM) / 4; i += ETHREADS) dst[i] = s[i];
    }
    for (int i = tid; i < OBSD * HDIM; i += ETHREADS) sm[E_T + i] = g_t[i];
    __syncthreads();

    // codebook squared norms
    if (tid < NCODE) {
        float s = 0.f;
        #pragma unroll
        for (int kk = 0; kk < CDIM; kk++) { float v = sm[E_CB + tid * CDIM + kk]; s = fmaf(v, v, s); }
        sm[E_CN + tid] = s;
    }

    // ---- h1 via PWL tables ----
    {
        const int r = tid >> 2, q = tid & 3;
        const int row = base + r;
        const int d = row & (OBSD - 1);
        const float x = sm[E_OB + r];
        const float* td = sm + E_T + d * HDIM;

        // s = #{ t_i < x }  (branchless lower bound with top guard)
        int seg;
        if (td[HDIM - 1] < x) seg = HDIM;
        else {
            seg = 0;
            #pragma unroll
            for (int w = HDIM / 2; w >= 1; w >>= 1)
                if (td[seg + w - 1] < x) seg += w;
        }

        const float* tab = g_tab + (size_t)(d * (HDIM + 1) + seg) * (2 * HDIM);
        const float4* Ap = (const float4*)(tab + q * 64);
        const float4* Bp = (const float4*)(tab + HDIM + q * 64);
        float* hp = sm + E_SH + r * 260 + q * 64;
        #pragma unroll 4
        for (int i = 0; i < 16; i++) {
            float4 a = Ap[i];
            float4 b = Bp[i];
            float4 h;
            h.x = fmaxf(fmaf(a.x, x, b.x), 0.f);
            h.y = fmaxf(fmaf(a.y, x, b.y), 0.f);
            h.z = fmaxf(fmaf(a.z, x, b.z), 0.f);
            h.w = fmaxf(fmaf(a.w, x, b.w), 0.f);
            *(float4*)(hp + i * 4) = h;
        }
    }
    __syncthreads();

    // ---- emb = h1 @ W2 + b2   (packed f32x2, column pairs) ----
    {
        const int r = tid >> 2, jg = tid & 3;
        u64 e2[2];
        e2[0] = f2pack(b2[jg * 4 + 0], b2[jg * 4 + 1]);
        e2[1] = f2pack(b2[jg * 4 + 2], b2[jg * 4 + 3]);
        const float* hrow = sm + E_SH + r * 260;
        const u64* wbase = (const u64*)(sm + E_W2) + jg * 2;
        #pragma unroll 4
        for (int c = 0; c < HDIM; c++) {
            float h = hrow[c];
            u64 h2 = f2pack(h, h);
            const u64* wp = wbase + c * (CDIM / 2);
            e2[0] = ffma2(h2, wp[0], e2[0]);
            e2[1] = ffma2(h2, wp[1], e2[1]);
        }
        u64* ep = (u64*)(sm + E_SE + r * CDIM + jg * 4);
        ep[0] = e2[0];
        ep[1] = e2[1];
    }
    __syncthreads();

    // ---- argmin over codes (||e||^2 dropped: argmin-invariant), write q ----
    {
        const int r = tid >> 2, part = tid & 3;
        u64 er2[8];
        const u64* ep = (const u64*)(sm + E_SE + r * CDIM);
        #pragma unroll
        for (int i = 0; i < 8; i++) er2[i] = ep[i];

        float best = 3.402823e38f; int bi = NCODE;
        const int j0 = part * (NCODE / 4);
        #pragma unroll 2
        for (int jj = 0; jj < NCODE / 4; jj++) {
            int j = j0 + jj;
            const u64* cp = (const u64*)(sm + E_CB + j * CDIM);
            u64 p0 = fmul2(er2[0], cp[0]);
            u64 p1 = fmul2(er2[1], cp[1]);
            p0 = ffma2(er2[2], cp[2], p0);
            p1 = ffma2(er2[3], cp[3], p1);
            p0 = ffma2(er2[4], cp[4], p0);
            p1 = ffma2(er2[5], cp[5], p1);
            p0 = ffma2(er2[6], cp[6], p0);
            p1 = ffma2(er2[7], cp[7], p1);
            u64 pz = fadd2(p0, p1);
            float dot = f2lo(pz) + f2hi(pz);
            float dist = fmaf(-2.f, dot, sm[E_CN + j]);
            if (dist < best) { best = dist; bi = j; }
        }
        #pragma unroll
        for (int off = 1; off < 4; off <<= 1) {
            float ob = __shfl_xor_sync(0xffffffffu, best, off);
            int   oi = __shfl_xor_sync(0xffffffffu, bi,   off);
            if (ob < best || (ob == best && oi < bi)) { best = ob; bi = oi; }
        }
        if (part == 0) {
            float4* dq = (float4*)&g_q[(size_t)(base + r) * CDIM];
            const float4* sc = (const float4*)(sm + E_CB + bi * CDIM);
            dq[0] = sc[0]; dq[1] = sc[1]; dq[2] = sc[2]; dq[3] = sc[3];
        }
    }
}

// ---------------- decoder shared-memory layout ----------------
#define D_ST    0
#define D_SA    9216
#define D_SB    10368
#define D_SMEM_FLOATS 18560
#define D_SMEM_BYTES  (D_SMEM_FLOATS * 4)

// ======================= fused 3-layer decoder (unchanged) =======================
__global__ __launch_bounds__(DTHREADS, 2)
void dec_kernel(const float* __restrict__ W0,
                const float* __restrict__ b0,
                const float* __restrict__ W1,
                const float* __restrict__ b1,
                const float* __restrict__ W2,
                const float* __restrict__ b2,
                float* __restrict__ out)
{
    extern __shared__ float sm[];
    const int tid  = threadIdx.x;
    const int base = blockIdx.x * DTR;
    const int cg   = tid & 31;
    const int rg   = tid >> 5;

    float acc[4][8];
    #pragma unroll
    for (int i = 0; i < 4; i++)
        #pragma unroll
        for (int j = 0; j < 8; j++) acc[i][j] = 0.f;

    for (int k0 = 0; k0 < 2 * HDIM; k0 += KC) {
        __syncthreads();
        {
            int r   = tid >> 3;
            int kk0 = (tid & 7) << 2;
            const float* src = g_q + (size_t)(base + r) * (2 * HDIM) + k0 + kk0;
            float4 v = *(const float4*)src;
            sm[D_SA + (kk0 + 0) * 36 + r] = v.x;
            sm[D_SA + (kk0 + 1) * 36 + r] = v.y;
            sm[D_SA + (kk0 + 2) * 36 + r] = v.z;
            sm[D_SA + (kk0 + 3) * 36 + r] = v.w;
        }
        {
            const float4* s = (const float4*)(W0 + k0 * HDIM);
            float4* d = (float4*)(sm + D_SB);
            #pragma unroll
            for (int i = 0; i < 8; i++) d[tid + i * DTHREADS] = s[tid + i * DTHREADS];
        }
        __syncthreads();
        #pragma unroll 8
        for (int kk = 0; kk < KC; kk++) {
            float4 av = *(const float4*)&sm[D_SA + kk * 36 + rg * 4];
            float a[4] = {av.x, av.y, av.z, av.w};
            float bb[8];
            #pragma unroll
            for (int i = 0; i < 8; i++) bb[i] = sm[D_SB + kk * HDIM + cg + 32 * i];
            #pragma unroll
            for (int ri = 0; ri < 4; ri++)
                #pragma unroll
                for (int ci = 0; ci < 8; ci++)
                    acc[ri][ci] = fmaf(a[ri], bb[ci], acc[ri][ci]);
        }
    }
    __syncthreads();
    {
        float bb[8];
        #pragma unroll
        for (int ci = 0; ci < 8; ci++) bb[ci] = b0[cg + 32 * ci];
        #pragma unroll
        for (int ci = 0; ci < 8; ci++) {
            int c = cg + 32 * ci;
            #pragma unroll
            for (int ri = 0; ri < 4; ri++)
                sm[D_ST + c * 36 + rg * 4 + ri] = fmaxf(acc[ri][ci] + bb[ci], 0.f);
        }
        #pragma unroll
        for (int i = 0; i < 4; i++)
            #pragma unroll
            for (int j = 0; j < 8; j++) acc[i][j] = 0.f;
    }

    for (int k0 = 0; k0 < HDIM; k0 += KC) {
        __syncthreads();
        {
            const float4* s = (const float4*)(W1 + k0 * HDIM);
            float4* d = (float4*)(sm + D_SB);
            #pragma unroll
            for (int i = 0; i < 8; i++) d[tid + i * DTHREADS] = s[tid + i * DTHREADS];
        }
        __syncthreads();
        #pragma unroll 8
        for (int kk = 0; kk < KC; kk++) {
            int k = k0 + kk;
            float4 av = *(const float4*)&sm[D_ST + k * 36 + rg * 4];
            float a[4] = {av.x, av.y, av.z, av.w};
            float bb[8];
            #pragma unroll
            for (int i = 0; i < 8; i++) bb[i] = sm[D_SB + kk * HDIM + cg + 32 * i];
            #pragma unroll
            for (int ri = 0; ri < 4; ri++)
                #pragma unroll
                for (int ci = 0; ci < 8; ci++)
                    acc[ri][ci] = fmaf(a[ri], bb[ci], acc[ri][ci]);
        }
    }
    __syncthreads();
    {
        float bb[8];
        #pragma unroll
        for (int ci = 0; ci < 8; ci++) bb[ci] = b1[cg + 32 * ci];
        #pragma unroll
        for (int ri = 0; ri < 4; ri++)
            #pragma unroll
            for (int ci = 0; ci < 8; ci++)
                sm[D_ST + (rg * 4 + ri) * 260 + cg + 32 * ci] =
                    fmaxf(acc[ri][ci] + bb[ci], 0.f);
        const float4* s = (const float4*)W2;
        float4* d = (float4*)(sm + D_SB);
        #pragma unroll
        for (int i = 0; i < 8; i++) d[tid + i * DTHREADS] = s[tid + i * DTHREADS];
    }
    __syncthreads();
    {
        int r = tid >> 3, part = tid & 7;
        int o0 = part * 4;
        float o[4];
        #pragma unroll
        for (int i = 0; i < 4; i++) o[i] = b2[o0 + i];
        #pragma unroll 4
        for (int c = 0; c < HDIM; c++) {
            float h = sm[D_ST + r * 260 + c];
            #pragma unroll
            for (int i = 0; i < 4; i++)
                o[i] = fmaf(h, sm[D_SB + c * OBSD + o0 + i], o[i]);
        }
        float4* dst = (float4*)&out[(size_t)(base + r) * OBSD + o0];
        *dst = make_float4(o[0], o[1], o[2], o[3]);
    }
}

// ======================= launcher =======================
extern "C" void kernel_launch(void* const* d_in, const int* in_sizes, int n_in,
                              void* d_out, int out_size) {
    (void)in_sizes; (void)n_in; (void)out_size;
    const float* obs = (const float*)d_in[0];
    const float* eW0 = (const float*)d_in[1];
    const float* eb0 = (const float*)d_in[2];
    const float* eW1 = (const float*)d_in[3];
    const float* eb1 = (const float*)d_in[4];
    const float* eW2 = (const float*)d_in[5];
    const float* eb2 = (const float*)d_in[6];
    const float* dW0 = (const float*)d_in[7];
    const float* db0 = (const float*)d_in[8];
    const float* dW1 = (const float*)d_in[9];
    const float* db1 = (const float*)d_in[10];
    const float* dW2 = (const float*)d_in[11];
    const float* db2 = (const float*)d_in[12];
    const float* cb  = (const float*)d_in[13];
    float* out = (float*)d_out;

    cudaFuncSetAttribute(enc_pwl_kernel,
                         cudaFuncAttributeMaxDynamicSharedMemorySize, E_SMEM_BYTES);
    cudaFuncSetAttribute(dec_kernel,
                         cudaFuncAttributeMaxDynamicSharedMemorySize, D_SMEM_BYTES);

    pwl_build_kernel<<<OBSD, HDIM>>>(eW0, eb0, eW1, eb1);
    enc_pwl_kernel<<<ROWS / ETR, ETHREADS, E_SMEM_BYTES>>>(obs, eW2, eb2, cb);
    dec_kernel<<<BATCH / DTR, DTHREADS, D_SMEM_BYTES>>>(
        dW0, db0, dW1, db1, dW2, db2, out);
}

// round 8
// speedup vs baseline: 2.4265x; 2.4265x over previous
#include <cuda_runtime.h>
#include <math_constants.h>

#define BATCH    8192
#define OBSD     32
#define HDIM     256
#define CDIM     16
#define NCODE    512
#define ROWS     (BATCH * OBSD)

#define ETR      128
#define ETHREADS 512
#define DTR      32
#define DTHREADS 256
#define KC       32

__device__ float g_q[(size_t)ROWS * CDIM];
__device__ float g_t[OBSD * HDIM];
__device__ float g_tab[(size_t)OBSD * (HDIM + 1) * (2 * HDIM)];

typedef unsigned long long u64;
__device__ __forceinline__ u64 f2pack(float lo, float hi) {
    u64 r; asm("mov.b64 %0, {%1, %2};" : "=l"(r) : "f"(lo), "f"(hi)); return r;
}
__device__ __forceinline__ u64 ffma2(u64 a, u64 b, u64 c) {
    u64 d; asm("fma.rn.f32x2 %0, %1, %2, %3;" : "=l"(d) : "l"(a), "l"(b), "l"(c)); return d;
}
__device__ __forceinline__ u64 fmul2(u64 a, u64 b) {
    u64 d; asm("mul.rn.f32x2 %0, %1, %2;" : "=l"(d) : "l"(a), "l"(b)); return d;
}
__device__ __forceinline__ u64 fadd2(u64 a, u64 b) {
    u64 d; asm("add.rn.f32x2 %0, %1, %2;" : "=l"(d) : "l"(a), "l"(b)); return d;
}
__device__ __forceinline__ float f2lo(u64 v) { return __uint_as_float((unsigned)v); }
__device__ __forceinline__ float f2hi(u64 v) { return __uint_as_float((unsigned)(v >> 32)); }
__device__ __forceinline__ u64 shfl_xor_u64(u64 v, int off) {
    unsigned lo = __shfl_xor_sync(0xffffffffu, (unsigned)v, off);
    unsigned hi = __shfl_xor_sync(0xffffffffu, (unsigned)(v >> 32), off);
    return ((u64)hi << 32) | lo;
}
__device__ __forceinline__ void kadd(float& s, float& c, float y) {
    float t = s + y;
    c += (fabsf(s) >= fabsf(y)) ? ((s - t) + y) : ((y - t) + s);
    s = t;
}

// ============ PWL table builder: grid = 32 d's x 4 j-quarters, 64 thr ============
__global__ void pwl_build_kernel(const float* __restrict__ W0,
                                 const float* __restrict__ b0,
                                 const float* __restrict__ W1,
                                 const float* __restrict__ b1)
{
    __shared__ float st[HDIM], swv[HDIM], scv[HDIM];
    __shared__ int   sord[HDIM], sact[HDIM];
    const int d  = blockIdx.x >> 2;
    const int jq = blockIdx.x & 3;
    const int t  = threadIdx.x;

    #pragma unroll
    for (int i = 0; i < 4; i++) {
        int k = i * 64 + t;
        float w = W0[k];
        float c = W0[(1 + d) * HDIM + k] + b0[k];
        int act; float tv;
        if (w > 0.f)      { act = 1; tv = -c / w; }
        else if (w < 0.f) { act = 0; tv = -c / w; }
        else              { act = (c <= 0.f) ? 1 : 0; tv = CUDART_INF_F; }
        st[k] = tv; swv[k] = w; scv[k] = c; sact[k] = act;
    }
    __syncthreads();
    #pragma unroll
    for (int i = 0; i < 4; i++) {
        int k = i * 64 + t;
        float tv = st[k];
        int rank = 0;
        for (int k2 = 0; k2 < HDIM; k2++) {
            float t2 = st[k2];
            rank += (t2 < tv || (t2 == tv && k2 < k)) ? 1 : 0;
        }
        sord[rank] = k;
        if (jq == 0) g_t[d * HDIM + rank] = tv;
    }
    __syncthreads();

    const int j = jq * 64 + t;
    float As = 0.f, Ac = 0.f, Bs = 0.f, Bc = 0.f;
    for (int kk0 = 0; kk0 < HDIM; kk0 += 8) {
        float w1v[8];
        #pragma unroll
        for (int u = 0; u < 8; u++) w1v[u] = W1[(kk0 + u) * HDIM + j];
        #pragma unroll
        for (int u = 0; u < 8; u++) {
            int kk = kk0 + u;
            if (!sact[kk]) {
                kadd(As, Ac, swv[kk] * w1v[u]);
                kadd(Bs, Bc, scv[kk] * w1v[u]);
            }
        }
    }
    const float bj = b1[j];
    float* tab = g_tab + (size_t)d * (HDIM + 1) * (2 * HDIM);
    tab[j] = As + Ac;
    tab[HDIM + j] = Bs + Bc + bj;
    for (int s0 = 1; s0 <= HDIM; s0 += 8) {
        int kks[8]; float w1v[8];
        #pragma unroll
        for (int u = 0; u < 8; u++) {
            kks[u] = sord[s0 - 1 + u];
            w1v[u] = W1[kks[u] * HDIM + j];
        }
        #pragma unroll
        for (int u = 0; u < 8; u++) {
            int kk = kks[u];
            float sgn = sact[kk] ? 1.f : -1.f;
            kadd(As, Ac, sgn * swv[kk] * w1v[u]);
            kadd(Bs, Bc, sgn * scv[kk] * w1v[u]);
            int s = s0 + u;
            tab[(size_t)s * (2 * HDIM) + j] = As + Ac;
            tab[(size_t)s * (2 * HDIM) + HDIM + j] = Bs + Bc + bj;
        }
    }
}

// ---------------- encoder smem layout (floats) ----------------
#define E_W2    0                  // 256 rows x 16, word-rotated by (c>>6)
#define E_CB    4096               // 512 x stride 18
#define E_CN    13312              // 512
#define E_SE    13824              // 128 x stride 18
#define E_OB    16128              // 128
#define E_T     16256              // 32 x 256
#define E_SMEM_FLOATS 24448
#define E_SMEM_BYTES  (E_SMEM_FLOATS * 4)   // 97792

__global__ __launch_bounds__(ETHREADS, 1)
void enc_pwl_kernel(const float* __restrict__ obs,
                    const float* __restrict__ W2,
                    const float* __restrict__ b2,
                    const float* __restrict__ cb)
{
    extern __shared__ float sm[];
    const int tid  = threadIdx.x;
    const int base = blockIdx.x * ETR;

    if (tid < ETR) sm[E_OB + tid] = obs[base + tid];
    // W2 with per-row word rotation: logical u64 word k of row c -> phys (k + (c>>6)) & 7
    for (int idx = tid; idx < HDIM * CDIM; idx += ETHREADS) {
        int c = idx >> 4, j = idx & 15;
        int phys = ((j >> 1) + (c >> 6)) & 7;
        sm[E_W2 + c * 16 + phys * 2 + (j & 1)] = W2[idx];
    }
    // codebook, stride 18
    for (int idx = tid; idx < NCODE * CDIM; idx += ETHREADS) {
        int j = idx >> 4, kk = idx & 15;
        sm[E_CB + j * 18 + kk] = cb[idx];
    }
    for (int i = tid; i < OBSD * HDIM; i += ETHREADS) sm[E_T + i] = g_t[i];
    __syncthreads();

    {   // code norms
        float s = 0.f;
        #pragma unroll
        for (int kk = 0; kk < CDIM; kk++) { float v = sm[E_CB + tid * 18 + kk]; s = fmaf(v, v, s); }
        sm[E_CN + tid] = s;
    }

    // ---- fused h1 + emb: thread (r, q) owns c-quarter q, full 16-wide e in regs ----
    {
        const int r = tid >> 2, q = tid & 3;
        const int d = (base + r) & (OBSD - 1);
        const float x = sm[E_OB + r];
        const float* td = sm + E_T + d * HDIM;
        int seg;
        if (td[HDIM - 1] < x) seg = HDIM;
        else {
            seg = 0;
            #pragma unroll
            for (int w = HDIM / 2; w >= 1; w >>= 1)
                if (td[seg + w - 1] < x) seg += w;
        }
        const float* tab = g_tab + (size_t)(d * (HDIM + 1) + seg) * (2 * HDIM);

        u64 e2[8];
        if (q == 0) {
            const u64* bp = (const u64*)b2;
            #pragma unroll
            for (int k = 0; k < 8; k++) e2[k] = bp[k];
        } else {
            #pragma unroll
            for (int k = 0; k < 8; k++) e2[k] = 0ull;
        }
        const float4* Ap = (const float4*)(tab + q * 64);
        const float4* Bp = (const float4*)(tab + HDIM + q * 64);
        #pragma unroll 4
        for (int i4 = 0; i4 < 16; i4++) {
            float4 a = Ap[i4];
            float4 b = Bp[i4];
            float hv[4];
            hv[0] = fmaxf(fmaf(a.x, x, b.x), 0.f);
            hv[1] = fmaxf(fmaf(a.y, x, b.y), 0.f);
            hv[2] = fmaxf(fmaf(a.z, x, b.z), 0.f);
            hv[3] = fmaxf(fmaf(a.w, x, b.w), 0.f);
            #pragma unroll
            for (int m = 0; m < 4; m++) {
                int c = q * 64 + i4 * 4 + m;
                u64 h2 = f2pack(hv[m], hv[m]);
                const u64* wp = (const u64*)(sm + E_W2 + c * 16);
                #pragma unroll
                for (int k = 0; k < 8; k++)
                    e2[k] = ffma2(h2, wp[(k + q) & 7], e2[k]);
            }
        }
        // butterfly-sum over the 4 q-lanes
        #pragma unroll
        for (int off = 1; off < 4; off <<= 1)
            #pragma unroll
            for (int k = 0; k < 8; k++)
                e2[k] = fadd2(e2[k], shfl_xor_u64(e2[k], off));
        if (q == 0) {
            u64* ep = (u64*)(sm + E_SE + r * 18);
            #pragma unroll
            for (int k = 0; k < 8; k++) ep[k] = e2[k];
        }
    }
    __syncthreads();

    // ---- distance + argmin: thread (g, p) = 4 rows x 32 codes (j = jj*16 + p) ----
    {
        const int g = tid >> 4, p = tid & 15;
        u64 er[4][8];
        #pragma unroll
        for (int row = 0; row < 4; row++) {
            const u64* ep = (const u64*)(sm + E_SE + (4 * g + row) * 18);
            #pragma unroll
            for (int k = 0; k < 8; k++) er[row][k] = ep[k];
        }
        float best[4]; int bi[4];
        #pragma unroll
        for (int row = 0; row < 4; row++) { best[row] = 3.402823e38f; bi[row] = NCODE; }

        for (int jj = 0; jj < NCODE / 16; jj++) {
            int j = jj * 16 + p;
            const u64* cp = (const u64*)(sm + E_CB + j * 18);
            u64 c0 = cp[0], c1 = cp[1], c2 = cp[2], c3 = cp[3];
            u64 c4 = cp[4], c5 = cp[5], c6 = cp[6], c7 = cp[7];
            float cn = sm[E_CN + j];
            #pragma unroll
            for (int row = 0; row < 4; row++) {
                u64 p0 = fmul2(er[row][0], c0);
                u64 p1 = fmul2(er[row][1], c1);
                p0 = ffma2(er[row][2], c2, p0);
                p1 = ffma2(er[row][3], c3, p1);
                p0 = ffma2(er[row][4], c4, p0);
                p1 = ffma2(er[row][5], c5, p1);
                p0 = ffma2(er[row][6], c6, p0);
                p1 = ffma2(er[row][7], c7, p1);
                u64 pz = fadd2(p0, p1);
                float dot = f2lo(pz) + f2hi(pz);
                float dist = fmaf(-2.f, dot, cn);
                if (dist < best[row]) { best[row] = dist; bi[row] = j; }
            }
        }
        // reduce over 16 p-lanes (lex: lowest index wins ties)
        #pragma unroll
        for (int off = 1; off < 16; off <<= 1) {
            #pragma unroll
            for (int row = 0; row < 4; row++) {
                float ob = __shfl_xor_sync(0xffffffffu, best[row], off);
                int   oi = __shfl_xor_sync(0xffffffffu, bi[row],   off);
                if (ob < best[row] || (ob == best[row] && oi < bi[row])) {
                    best[row] = ob; bi[row] = oi;
                }
            }
        }
        if (p == 0) {
            #pragma unroll
            for (int row = 0; row < 4; row++) {
                const u64* sc = (const u64*)(sm + E_CB + bi[row] * 18);
                u64* dq = (u64*)&g_q[(size_t)(base + 4 * g + row) * CDIM];
                #pragma unroll
                for (int k = 0; k < 8; k++) dq[k] = sc[k];
            }
        }
    }
}

// ---------------- decoder (unchanged) ----------------
#define D_ST    0
#define D_SA    9216
#define D_SB    10368
#define D_SMEM_FLOATS 18560
#define D_SMEM_BYTES  (D_SMEM_FLOATS * 4)

__global__ __launch_bounds__(DTHREADS, 2)
void dec_kernel(const float* __restrict__ W0,
                const float* __restrict__ b0,
                const float* __restrict__ W1,
                const float* __restrict__ b1,
                const float* __restrict__ W2,
                const float* __restrict__ b2,
                float* __restrict__ out)
{
    extern __shared__ float sm[];
    const int tid  = threadIdx.x;
    const int base = blockIdx.x * DTR;
    const int cg   = tid & 31;
    const int rg   = tid >> 5;

    float acc[4][8];
    #pragma unroll
    for (int i = 0; i < 4; i++)
        #pragma unroll
        for (int j = 0; j < 8; j++) acc[i][j] = 0.f;

    for (int k0 = 0; k0 < 2 * HDIM; k0 += KC) {
        __syncthreads();
        {
            int r   = tid >> 3;
            int kk0 = (tid & 7) << 2;
            const float* src = g_q + (size_t)(base + r) * (2 * HDIM) + k0 + kk0;
            float4 v = *(const float4*)src;
            sm[D_SA + (kk0 + 0) * 36 + r] = v.x;
            sm[D_SA + (kk0 + 1) * 36 + r] = v.y;
            sm[D_SA + (kk0 + 2) * 36 + r] = v.z;
            sm[D_SA + (kk0 + 3) * 36 + r] = v.w;
        }
        {
            const float4* s = (const float4*)(W0 + k0 * HDIM);
            float4* d = (float4*)(sm + D_SB);
            #pragma unroll
            for (int i = 0; i < 8; i++) d[tid + i * DTHREADS] = s[tid + i * DTHREADS];
        }
        __syncthreads();
        #pragma unroll 8
        for (int kk = 0; kk < KC; kk++) {
            float4 av = *(const float4*)&sm[D_SA + kk * 36 + rg * 4];
            float a[4] = {av.x, av.y, av.z, av.w};
            float bb[8];
            #pragma unroll
            for (int i = 0; i < 8; i++) bb[i] = sm[D_SB + kk * HDIM + cg + 32 * i];
            #pragma unroll
            for (int ri = 0; ri < 4; ri++)
                #pragma unroll
                for (int ci = 0; ci < 8; ci++)
                    acc[ri][ci] = fmaf(a[ri], bb[ci], acc[ri][ci]);
        }
    }
    __syncthreads();
    {
        float bb[8];
        #pragma unroll
        for (int ci = 0; ci < 8; ci++) bb[ci] = b0[cg + 32 * ci];
        #pragma unroll
        for (int ci = 0; ci < 8; ci++) {
            int c = cg + 32 * ci;
            #pragma unroll
            for (int ri = 0; ri < 4; ri++)
                sm[D_ST + c * 36 + rg * 4 + ri] = fmaxf(acc[ri][ci] + bb[ci], 0.f);
        }
        #pragma unroll
        for (int i = 0; i < 4; i++)
            #pragma unroll
            for (int j = 0; j < 8; j++) acc[i][j] = 0.f;
    }

    for (int k0 = 0; k0 < HDIM; k0 += KC) {
        __syncthreads();
        {
            const float4* s = (const float4*)(W1 + k0 * HDIM);
            float4* d = (float4*)(sm + D_SB);
            #pragma unroll
            for (int i = 0; i < 8; i++) d[tid + i * DTHREADS] = s[tid + i * DTHREADS];
        }
        __syncthreads();
        #pragma unroll 8
        for (int kk = 0; kk < KC; kk++) {
            int k = k0 + kk;
            float4 av = *(const float4*)&sm[D_ST + k * 36 + rg * 4];
            float a[4] = {av.x, av.y, av.z, av.w};
            float bb[8];
            #pragma unroll
            for (int i = 0; i < 8; i++) bb[i] = sm[D_SB + kk * HDIM + cg + 32 * i];
            #pragma unroll
            for (int ri = 0; ri < 4; ri++)
                #pragma unroll
                for (int ci = 0; ci < 8; ci++)
                    acc[ri][ci] = fmaf(a[ri], bb[ci], acc[ri][ci]);
        }
    }
    __syncthreads();
    {
        float bb[8];
        #pragma unroll
        for (int ci = 0; ci < 8; ci++) bb[ci] = b1[cg + 32 * ci];
        #pragma unroll
        for (int ri = 0; ri < 4; ri++)
            #pragma unroll
            for (int ci = 0; ci < 8; ci++)
                sm[D_ST + (rg * 4 + ri) * 260 + cg + 32 * ci] =
                    fmaxf(acc[ri][ci] + bb[ci], 0.f);
        const float4* s = (const float4*)W2;
        float4* d = (float4*)(sm + D_SB);
        #pragma unroll
        for (int i = 0; i < 8; i++) d[tid + i * DTHREADS] = s[tid + i * DTHREADS];
    }
    __syncthreads();
    {
        int r = tid >> 3, part = tid & 7;
        int o0 = part * 4;
        float o[4];
        #pragma unroll
        for (int i = 0; i < 4; i++) o[i] = b2[o0 + i];
        #pragma unroll 4
        for (int c = 0; c < HDIM; c++) {
            float h = sm[D_ST + r * 260 + c];
            #pragma unroll
            for (int i = 0; i < 4; i++)
                o[i] = fmaf(h, sm[D_SB + c * OBSD + o0 + i], o[i]);
        }
        float4* dst = (float4*)&out[(size_t)(base + r) * OBSD + o0];
        *dst = make_float4(o[0], o[1], o[2], o[3]);
    }
}

// ======================= launcher =======================
extern "C" void kernel_launch(void* const* d_in, const int* in_sizes, int n_in,
                              void* d_out, int out_size) {
    (void)in_sizes; (void)n_in; (void)out_size;
    const float* obs = (const float*)d_in[0];
    const float* eW0 = (const float*)d_in[1];
    const float* eb0 = (const float*)d_in[2];
    const float* eW1 = (const float*)d_in[3];
    const float* eb1 = (const float*)d_in[4];
    const float* eW2 = (const float*)d_in[5];
    const float* eb2 = (const float*)d_in[6];
    const float* dW0 = (const float*)d_in[7];
    const float* db0 = (const float*)d_in[8];
    const float* dW1 = (const float*)d_in[9];
    const float* db1 = (const float*)d_in[10];
    const float* dW2 = (const float*)d_in[11];
    const float* db2 = (const float*)d_in[12];
    const float* cb  = (const float*)d_in[13];
    float* out = (float*)d_out;

    cudaFuncSetAttribute(enc_pwl_kernel,
                         cudaFuncAttributeMaxDynamicSharedMemorySize, E_SMEM_BYTES);
    cudaFuncSetAttribute(dec_kernel,
                         cudaFuncAttributeMaxDynamicSharedMemorySize, D_SMEM_BYTES);

    pwl_build_kernel<<<OBSD * 4, 64>>>(eW0, eb0, eW1, eb1);
    enc_pwl_kernel<<<ROWS / ETR, ETHREADS, E_SMEM_BYTES>>>(obs, eW2, eb2, cb);
    dec_kernel<<<BATCH / DTR, DTHREADS, D_SMEM_BYTES>>>(
        dW0, db0, dW1, db1, dW2, db2, out);
}

// round 9
// speedup vs baseline: 2.7568x; 1.1361x over previous
#include <cuda_runtime.h>
#include <math_constants.h>

#define BATCH    8192
#define OBSD     32
#define HDIM     256
#define CDIM     16
#define NCODE    512
#define ROWS     (BATCH * OBSD)

#define ETR      128
#define ETHREADS 512
#define DTR      32
#define DTHREADS 256
#define KC       32

__device__ float g_q[(size_t)ROWS * CDIM];
__device__ float g_t[OBSD * HDIM];
__device__ float g_tab[(size_t)OBSD * (HDIM + 1) * (2 * HDIM)];

typedef unsigned long long u64;
__device__ __forceinline__ u64 f2pack(float lo, float hi) {
    u64 r; asm("mov.b64 %0, {%1, %2};" : "=l"(r) : "f"(lo), "f"(hi)); return r;
}
__device__ __forceinline__ u64 ffma2(u64 a, u64 b, u64 c) {
    u64 d; asm("fma.rn.f32x2 %0, %1, %2, %3;" : "=l"(d) : "l"(a), "l"(b), "l"(c)); return d;
}
__device__ __forceinline__ u64 fmul2(u64 a, u64 b) {
    u64 d; asm("mul.rn.f32x2 %0, %1, %2;" : "=l"(d) : "l"(a), "l"(b)); return d;
}
__device__ __forceinline__ u64 fadd2(u64 a, u64 b) {
    u64 d; asm("add.rn.f32x2 %0, %1, %2;" : "=l"(d) : "l"(a), "l"(b)); return d;
}
__device__ __forceinline__ float f2lo(u64 v) { return __uint_as_float((unsigned)v); }
__device__ __forceinline__ float f2hi(u64 v) { return __uint_as_float((unsigned)(v >> 32)); }
__device__ __forceinline__ u64 shfl_xor_u64(u64 v, int off) {
    unsigned lo = __shfl_xor_sync(0xffffffffu, (unsigned)v, off);
    unsigned hi = __shfl_xor_sync(0xffffffffu, (unsigned)(v >> 32), off);
    return ((u64)hi << 32) | lo;
}
__device__ __forceinline__ void kadd(float& s, float& c, float y) {
    float t = s + y;
    c += (fabsf(s) >= fabsf(y)) ? ((s - t) + y) : ((y - t) + s);
    s = t;
}

// ============ PWL builder: grid = 32 d x 4 jq, 256 thr, W1 quarter staged in smem ============
// dyn smem (floats): st 0..255 | swv 256.. | scv 512.. | meta(ints) 768..1279 | W1S 1280..17663
#define P_ST   0
#define P_SW   256
#define P_SC   512
#define P_ORD  768      // int
#define P_ACT  1024     // int
#define P_W1S  1280     // [256 rows][64 cols]
#define P_SMEM_FLOATS (1280 + 256 * 64)
#define P_SMEM_BYTES  (P_SMEM_FLOATS * 4)    // 70656

__global__ __launch_bounds__(256, 1)
void pwl_build_kernel(const float* __restrict__ W0,
                      const float* __restrict__ b0,
                      const float* __restrict__ W1,
                      const float* __restrict__ b1)
{
    extern __shared__ float ps[];
    int*  pord = (int*)(ps + P_ORD);
    int*  pact = (int*)(ps + P_ACT);
    const int d  = blockIdx.x >> 2;
    const int jq = blockIdx.x & 3;
    const int t  = threadIdx.x;

    // breakpoints for k = t
    {
        float w = W0[t];
        float c = W0[(1 + d) * HDIM + t] + b0[t];
        int act; float tv;
        if (w > 0.f)      { act = 1; tv = -c / w; }
        else if (w < 0.f) { act = 0; tv = -c / w; }
        else              { act = (c <= 0.f) ? 1 : 0; tv = CUDART_INF_F; }
        ps[P_ST + t] = tv; ps[P_SW + t] = w; ps[P_SC + t] = c; pact[t] = act;
    }
    // stage W1 j-quarter: W1S[kk][jj] = W1[kk*256 + jq*64 + jj]; thread t loads row t (64 floats)
    {
        const float4* src = (const float4*)(W1 + t * HDIM + jq * 64);
        float4* dst = (float4*)(ps + P_W1S + t * 64);
        #pragma unroll
        for (int i = 0; i < 16; i++) dst[i] = src[i];
    }
    __syncthreads();
    // rank
    {
        float tv = ps[P_ST + t];
        int rank = 0;
        for (int k2 = 0; k2 < HDIM; k2++) {
            float t2 = ps[P_ST + k2];
            rank += (t2 < tv || (t2 == tv && k2 < t)) ? 1 : 0;
        }
        pord[rank] = t;
        if (jq == 0) g_t[d * HDIM + rank] = tv;
    }
    __syncthreads();

    if (t < 64) {
        const int j = jq * 64 + t;
        float As = 0.f, Ac = 0.f, Bs = 0.f, Bc = 0.f;
        // segment 0
        for (int kk = 0; kk < HDIM; kk++) {
            if (!pact[kk]) {
                float w1v = ps[P_W1S + kk * 64 + t];
                kadd(As, Ac, ps[P_SW + kk] * w1v);
                kadd(Bs, Bc, ps[P_SC + kk] * w1v);
            }
        }
        const float bj = b1[j];
        float* tab = g_tab + (size_t)d * (HDIM + 1) * (2 * HDIM);
        tab[j] = As + Ac;
        tab[HDIM + j] = Bs + Bc + bj;
        // segments 1..256
        for (int s = 1; s <= HDIM; s++) {
            int kk = pord[s - 1];
            float w1v = ps[P_W1S + kk * 64 + t];
            float sgn = pact[kk] ? 1.f : -1.f;
            kadd(As, Ac, sgn * ps[P_SW + kk] * w1v);
            kadd(Bs, Bc, sgn * ps[P_SC + kk] * w1v);
            tab[(size_t)s * (2 * HDIM) + j] = As + Ac;
            tab[(size_t)s * (2 * HDIM) + HDIM + j] = Bs + Bc + bj;
        }
    }
}

// ---------------- encoder smem layout (floats) ----------------
#define E_W2    0                  // 256 rows x 16, u64-word rotated by (c>>6)
#define E_CB    4096               // 512 x stride 18
#define E_CN    13312              // 512
#define E_SE    13824              // 128 x stride 18
#define E_OB    16128              // 128
#define E_T     16256              // 32 x 256
#define E_SMEM_FLOATS 24448
#define E_SMEM_BYTES  (E_SMEM_FLOATS * 4)   // 97792 -> 2 CTAs/SM

__global__ __launch_bounds__(ETHREADS, 2)
void enc_pwl_kernel(const float* __restrict__ obs,
                    const float* __restrict__ W2,
                    const float* __restrict__ b2,
                    const float* __restrict__ cb)
{
    extern __shared__ float sm[];
    const int tid  = threadIdx.x;
    const int base = blockIdx.x * ETR;

    if (tid < ETR) sm[E_OB + tid] = obs[base + tid];
    for (int idx = tid; idx < HDIM * CDIM; idx += ETHREADS) {
        int c = idx >> 4, j = idx & 15;
        int phys = ((j >> 1) + (c >> 6)) & 7;
        sm[E_W2 + c * 16 + phys * 2 + (j & 1)] = W2[idx];
    }
    for (int idx = tid; idx < NCODE * CDIM; idx += ETHREADS) {
        int j = idx >> 4, kk = idx & 15;
        sm[E_CB + j * 18 + kk] = cb[idx];
    }
    for (int i = tid; i < OBSD * HDIM; i += ETHREADS) sm[E_T + i] = g_t[i];
    __syncthreads();

    {   // code norms
        float s = 0.f;
        #pragma unroll
        for (int kk = 0; kk < CDIM; kk++) { float v = sm[E_CB + tid * 18 + kk]; s = fmaf(v, v, s); }
        sm[E_CN + tid] = s;
    }

    // ---- fused h1 + emb: thread (r, q) owns c-quarter q, full 16-wide e in regs ----
    {
        const int r = tid >> 2, q = tid & 3;
        const int d = (base + r) & (OBSD - 1);
        const float x = sm[E_OB + r];
        const float* td = sm + E_T + d * HDIM;
        int seg;
        if (td[HDIM - 1] < x) seg = HDIM;
        else {
            seg = 0;
            #pragma unroll
            for (int w = HDIM / 2; w >= 1; w >>= 1)
                if (td[seg + w - 1] < x) seg += w;
        }
        const float* tab = g_tab + (size_t)(d * (HDIM + 1) + seg) * (2 * HDIM);

        u64 e2[8];
        if (q == 0) {
            const u64* bp = (const u64*)b2;
            #pragma unroll
            for (int k = 0; k < 8; k++) e2[k] = bp[k];
        } else {
            #pragma unroll
            for (int k = 0; k < 8; k++) e2[k] = 0ull;
        }
        const float4* Ap = (const float4*)(tab + q * 64);
        const float4* Bp = (const float4*)(tab + HDIM + q * 64);
        #pragma unroll 4
        for (int i4 = 0; i4 < 16; i4++) {
            float4 a = Ap[i4];
            float4 b = Bp[i4];
            float hv[4];
            hv[0] = fmaxf(fmaf(a.x, x, b.x), 0.f);
            hv[1] = fmaxf(fmaf(a.y, x, b.y), 0.f);
            hv[2] = fmaxf(fmaf(a.z, x, b.z), 0.f);
            hv[3] = fmaxf(fmaf(a.w, x, b.w), 0.f);
            #pragma unroll
            for (int m = 0; m < 4; m++) {
                int c = q * 64 + i4 * 4 + m;
                u64 h2 = f2pack(hv[m], hv[m]);
                const u64* wp = (const u64*)(sm + E_W2 + c * 16);
                #pragma unroll
                for (int k = 0; k < 8; k++)
                    e2[k] = ffma2(h2, wp[(k + q) & 7], e2[k]);
            }
        }
        #pragma unroll
        for (int off = 1; off < 4; off <<= 1)
            #pragma unroll
            for (int k = 0; k < 8; k++)
                e2[k] = fadd2(e2[k], shfl_xor_u64(e2[k], off));
        if (q == 0) {
            u64* ep = (u64*)(sm + E_SE + r * 18);
            #pragma unroll
            for (int k = 0; k < 8; k++) ep[k] = e2[k];
        }
    }
    __syncthreads();

    // ---- distance + argmin: thread (g, p) = 2 rows x 64 codes (j = jj*8 + p) ----
    {
        const int g = tid >> 3, p = tid & 7;
        u64 er[2][8];
        #pragma unroll
        for (int row = 0; row < 2; row++) {
            const u64* ep = (const u64*)(sm + E_SE + (2 * g + row) * 18);
            #pragma unroll
            for (int k = 0; k < 8; k++) er[row][k] = ep[k];
        }
        float best[2]; int bi[2];
        #pragma unroll
        for (int row = 0; row < 2; row++) { best[row] = 3.402823e38f; bi[row] = NCODE; }

        for (int jj = 0; jj < NCODE / 8; jj++) {
            int j = jj * 8 + p;
            const u64* cp = (const u64*)(sm + E_CB + j * 18);
            u64 c0 = cp[0], c1 = cp[1], c2 = cp[2], c3 = cp[3];
            u64 c4 = cp[4], c5 = cp[5], c6 = cp[6], c7 = cp[7];
            float cn = sm[E_CN + j];
            #pragma unroll
            for (int row = 0; row < 2; row++) {
                u64 p0 = fmul2(er[row][0], c0);
                u64 p1 = fmul2(er[row][1], c1);
                p0 = ffma2(er[row][2], c2, p0);
                p1 = ffma2(er[row][3], c3, p1);
                p0 = ffma2(er[row][4], c4, p0);
                p1 = ffma2(er[row][5], c5, p1);
                p0 = ffma2(er[row][6], c6, p0);
                p1 = ffma2(er[row][7], c7, p1);
                u64 pz = fadd2(p0, p1);
                float dot = f2lo(pz) + f2hi(pz);
                float dist = fmaf(-2.f, dot, cn);
                if (dist < best[row]) { best[row] = dist; bi[row] = j; }
            }
        }
        #pragma unroll
        for (int off = 1; off < 8; off <<= 1) {
            #pragma unroll
            for (int row = 0; row < 2; row++) {
                float ob = __shfl_xor_sync(0xffffffffu, best[row], off);
                int   oi = __shfl_xor_sync(0xffffffffu, bi[row],   off);
                if (ob < best[row] || (ob == best[row] && oi < bi[row])) {
                    best[row] = ob; bi[row] = oi;
                }
            }
        }
        if (p == 0) {
            #pragma unroll
            for (int row = 0; row < 2; row++) {
                const u64* sc = (const u64*)(sm + E_CB + bi[row] * 18);
                u64* dq = (u64*)&g_q[(size_t)(base + 2 * g + row) * CDIM];
                #pragma unroll
                for (int k = 0; k < 8; k++) dq[k] = sc[k];
            }
        }
    }
}

// ---------------- decoder (unchanged) ----------------
#define D_ST    0
#define D_SA    9216
#define D_SB    10368
#define D_SMEM_FLOATS 18560
#define D_SMEM_BYTES  (D_SMEM_FLOATS * 4)

__global__ __launch_bounds__(DTHREADS, 2)
void dec_kernel(const float* __restrict__ W0,
                const float* __restrict__ b0,
                const float* __restrict__ W1,
                const float* __restrict__ b1,
                const float* __restrict__ W2,
                const float* __restrict__ b2,
                float* __restrict__ out)
{
    extern __shared__ float sm[];
    const int tid  = threadIdx.x;
    const int base = blockIdx.x * DTR;
    const int cg   = tid & 31;
    const int rg   = tid >> 5;

    float acc[4][8];
    #pragma unroll
    for (int i = 0; i < 4; i++)
        #pragma unroll
        for (int j = 0; j < 8; j++) acc[i][j] = 0.f;

    for (int k0 = 0; k0 < 2 * HDIM; k0 += KC) {
        __syncthreads();
        {
            int r   = tid >> 3;
            int kk0 = (tid & 7) << 2;
            const float* src = g_q + (size_t)(base + r) * (2 * HDIM) + k0 + kk0;
            float4 v = *(const float4*)src;
            sm[D_SA + (kk0 + 0) * 36 + r] = v.x;
            sm[D_SA + (kk0 + 1) * 36 + r] = v.y;
            sm[D_SA + (kk0 + 2) * 36 + r] = v.z;
            sm[D_SA + (kk0 + 3) * 36 + r] = v.w;
        }
        {
            const float4* s = (const float4*)(W0 + k0 * HDIM);
            float4* d = (float4*)(sm + D_SB);
            #pragma unroll
            for (int i = 0; i < 8; i++) d[tid + i * DTHREADS] = s[tid + i * DTHREADS];
        }
        __syncthreads();
        #pragma unroll 8
        for (int kk = 0; kk < KC; kk++) {
            float4 av = *(const float4*)&sm[D_SA + kk * 36 + rg * 4];
            float a[4] = {av.x, av.y, av.z, av.w};
            float bb[8];
            #pragma unroll
            for (int i = 0; i < 8; i++) bb[i] = sm[D_SB + kk * HDIM + cg + 32 * i];
            #pragma unroll
            for (int ri = 0; ri < 4; ri++)
                #pragma unroll
                for (int ci = 0; ci < 8; ci++)
                    acc[ri][ci] = fmaf(a[ri], bb[ci], acc[ri][ci]);
        }
    }
    __syncthreads();
    {
        float bb[8];
        #pragma unroll
        for (int ci = 0; ci < 8; ci++) bb[ci] = b0[cg + 32 * ci];
        #pragma unroll
        for (int ci = 0; ci < 8; ci++) {
            int c = cg + 32 * ci;
            #pragma unroll
            for (int ri = 0; ri < 4; ri++)
                sm[D_ST + c * 36 + rg * 4 + ri] = fmaxf(acc[ri][ci] + bb[ci], 0.f);
        }
        #pragma unroll
        for (int i = 0; i < 4; i++)
            #pragma unroll
            for (int j = 0; j < 8; j++) acc[i][j] = 0.f;
    }

    for (int k0 = 0; k0 < HDIM; k0 += KC) {
        __syncthreads();
        {
            const float4* s = (const float4*)(W1 + k0 * HDIM);
            float4* d = (float4*)(sm + D_SB);
            #pragma unroll
            for (int i = 0; i < 8; i++) d[tid + i * DTHREADS] = s[tid + i * DTHREADS];
        }
        __syncthreads();
        #pragma unroll 8
        for (int kk = 0; kk < KC; kk++) {
            int k = k0 + kk;
            float4 av = *(const float4*)&sm[D_ST + k * 36 + rg * 4];
            float a[4] = {av.x, av.y, av.z, av.w};
            float bb[8];
            #pragma unroll
            for (int i = 0; i < 8; i++) bb[i] = sm[D_SB + kk * HDIM + cg + 32 * i];
            #pragma unroll
            for (int ri = 0; ri < 4; ri++)
                #pragma unroll
                for (int ci = 0; ci < 8; ci++)
                    acc[ri][ci] = fmaf(a[ri], bb[ci], acc[ri][ci]);
        }
    }
    __syncthreads();
    {
        float bb[8];
        #pragma unroll
        for (int ci = 0; ci < 8; ci++) bb[ci] = b1[cg + 32 * ci];
        #pragma unroll
        for (int ri = 0; ri < 4; ri++)
            #pragma unroll
            for (int ci = 0; ci < 8; ci++)
                sm[D_ST + (rg * 4 + ri) * 260 + cg + 32 * ci] =
                    fmaxf(acc[ri][ci] + bb[ci], 0.f);
        const float4* s = (const float4*)W2;
        float4* d = (float4*)(sm + D_SB);
        #pragma unroll
        for (int i = 0; i < 8; i++) d[tid + i * DTHREADS] = s[tid + i * DTHREADS];
    }
    __syncthreads();
    {
        int r = tid >> 3, part = tid & 7;
        int o0 = part * 4;
        float o[4];
        #pragma unroll
        for (int i = 0; i < 4; i++) o[i] = b2[o0 + i];
        #pragma unroll 4
        for (int c = 0; c < HDIM; c++) {
            float h = sm[D_ST + r * 260 + c];
            #pragma unroll
            for (int i = 0; i < 4; i++)
                o[i] = fmaf(h, sm[D_SB + c * OBSD + o0 + i], o[i]);
        }
        float4* dst = (float4*)&out[(size_t)(base + r) * OBSD + o0];
        *dst = make_float4(o[0], o[1], o[2], o[3]);
    }
}

// ======================= launcher =======================
extern "C" void kernel_launch(void* const* d_in, const int* in_sizes, int n_in,
                              void* d_out, int out_size) {
    (void)in_sizes; (void)n_in; (void)out_size;
    const float* obs = (const float*)d_in[0];
    const float* eW0 = (const float*)d_in[1];
    const float* eb0 = (const float*)d_in[2];
    const float* eW1 = (const float*)d_in[3];
    const float* eb1 = (const float*)d_in[4];
    const float* eW2 = (const float*)d_in[5];
    const float* eb2 = (const float*)d_in[6];
    const float* dW0 = (const float*)d_in[7];
    const float* db0 = (const float*)d_in[8];
    const float* dW1 = (const float*)d_in[9];
    const float* db1 = (const float*)d_in[10];
    const float* dW2 = (const float*)d_in[11];
    const float* db2 = (const float*)d_in[12];
    const float* cb  = (const float*)d_in[13];
    float* out = (float*)d_out;

    cudaFuncSetAttribute(pwl_build_kernel,
                         cudaFuncAttributeMaxDynamicSharedMemorySize, P_SMEM_BYTES);
    cudaFuncSetAttribute(enc_pwl_kernel,
                         cudaFuncAttributeMaxDynamicSharedMemorySize, E_SMEM_BYTES);
    cudaFuncSetAttribute(dec_kernel,
                         cudaFuncAttributeMaxDynamicSharedMemorySize, D_SMEM_BYTES);

    pwl_build_kernel<<<OBSD * 4, 256, P_SMEM_BYTES>>>(eW0, eb0, eW1, eb1);
    enc_pwl_kernel<<<ROWS / ETR, ETHREADS, E_SMEM_BYTES>>>(obs, eW2, eb2, cb);
    dec_kernel<<<BATCH / DTR, DTHREADS, D_SMEM_BYTES>>>(
        dW0, db0, dW1, db1, dW2, db2, out);
}